// round 1
// baseline (speedup 1.0000x reference)
#include <cuda_runtime.h>
#include <math.h>

// Problem constants
#define B_  32
#define T_  256
#define D_  1024
#define M_  256
#define S_  64
#define ROWS_ (B_*S_)     // 2048
#define BT_  (B_*T_)      // 8192

// ---------------- scratch (static device globals; no allocation) ----------------
// g_mv: [BT, 512] : cols [0,256) = mem_input (x@Wi.T+bi), cols [256,512) = vals (x@Wv.T+bv)
__device__ float g_mv[(size_t)BT_ * 512];
// g_vproj: [BT, 768] : vals @ {Wr_x,Wz_x,Wu_x}.T + {br,bz,bu}  (gate-major: 0..255 r, 256..511 z, 512..767 u)
__device__ float g_vproj[(size_t)BT_ * 768];
// per-step intermediates
__device__ float g_rm[(size_t)ROWS_ * M_];   // r * mem
__device__ float g_zg[(size_t)ROWS_ * M_];   // z gate
__device__ float g_ww[ROWS_];                // write weights (softmax)
__device__ float g_usage[ROWS_];             // usage state
// packed weights
__device__ float g_Wiv[(size_t)512 * D_];    // rows 0..255 Wi, 256..511 Wv   [512,1024]
__device__ float g_biv[512];
__device__ float g_Wx[(size_t)768 * M_];     // x-halves of Wr,Wz,Wu  [768,256]
__device__ float g_Wh[(size_t)768 * M_];     // h-halves of Wr,Wz,Wu  [768,256]
__device__ float g_bx[768];

// ---------------- pack kernel ----------------
__global__ void k_pack(const float* __restrict__ Wi, const float* __restrict__ bi,
                       const float* __restrict__ Wv, const float* __restrict__ bv,
                       const float* __restrict__ Wr, const float* __restrict__ br,
                       const float* __restrict__ Wz, const float* __restrict__ bz,
                       const float* __restrict__ Wu, const float* __restrict__ bu)
{
    int idx = blockIdx.x * blockDim.x + threadIdx.x;   // grid covers 524288
    if (idx < 512 * 1024) {
        int r = idx >> 10, k = idx & 1023;
        g_Wiv[idx] = (r < 256) ? Wi[r * 1024 + k] : Wv[(r - 256) * 1024 + k];
    }
    if (idx < 768 * 256) {
        int n = idx >> 8, k = idx & 255;
        int gate = n >> 8, j = n & 255;
        const float* Wg = (gate == 0) ? Wr : ((gate == 1) ? Wz : Wu);
        g_Wx[idx] = Wg[j * 512 + k];
        g_Wh[idx] = Wg[j * 512 + 256 + k];
    }
    if (idx < 768) {
        g_bx[idx] = (idx < 256) ? br[idx] : ((idx < 512) ? bz[idx - 256] : bu[idx - 512]);
    }
    if (idx < 512) {
        g_biv[idx] = (idx < 256) ? bi[idx] : bv[idx - 256];
    }
}

// ---------------- shared 64x64x16 fp32 GEMM tile core ----------------
// acc[i][j] += sum_k A[row0+ty*4+i][k] * W[n0+tx*4+j][k]   (both operands K-major)
template<int KTILE>
__device__ __forceinline__ void gemm_tile(const float* __restrict__ A, int lda,
                                          const float* __restrict__ W, int ldw,
                                          int K, int row0, int n0, float acc[4][4])
{
    __shared__ float sA[KTILE][68];
    __shared__ float sW[KTILE][68];
    const int tid = threadIdx.x;
    const int lr = tid >> 2;            // 0..63
    const int lk = (tid & 3) * 4;       // 0,4,8,12
    const int ty = tid >> 4;            // 0..15
    const int tx = tid & 15;            // 0..15
    for (int k0 = 0; k0 < K; k0 += KTILE) {
        float4 av = *(const float4*)(A + (size_t)(row0 + lr) * lda + k0 + lk);
        float4 wv = *(const float4*)(W + (size_t)(n0 + lr) * ldw + k0 + lk);
        __syncthreads();
        sA[lk + 0][lr] = av.x; sA[lk + 1][lr] = av.y; sA[lk + 2][lr] = av.z; sA[lk + 3][lr] = av.w;
        sW[lk + 0][lr] = wv.x; sW[lk + 1][lr] = wv.y; sW[lk + 2][lr] = wv.z; sW[lk + 3][lr] = wv.w;
        __syncthreads();
        #pragma unroll
        for (int kk = 0; kk < KTILE; kk++) {
            float4 a = *(const float4*)&sA[kk][ty * 4];
            float4 w = *(const float4*)&sW[kk][tx * 4];
            float ar[4] = {a.x, a.y, a.z, a.w};
            float wr[4] = {w.x, w.y, w.z, w.w};
            #pragma unroll
            for (int i = 0; i < 4; i++)
                #pragma unroll
                for (int j = 0; j < 4; j++)
                    acc[i][j] = fmaf(ar[i], wr[j], acc[i][j]);
        }
    }
}

// ---------------- precompute GEMMs ----------------
// mode 0: g_mv[8192,512]   = hidden[8192,1024] @ g_Wiv.T + g_biv
// mode 1: g_vproj[8192,768] = vals[8192,256]    @ g_Wx.T  + g_bx
__global__ void k_gemm_pre(const float* __restrict__ hidden, int mode)
{
    const float* A; const float* W; const float* bias; float* C;
    int lda, ldw, ldc, K, ntn;
    if (mode == 0) { A = hidden;     lda = 1024; W = g_Wiv; ldw = 1024; bias = g_biv; C = g_mv;    ldc = 512; K = 1024; ntn = 8;  }
    else           { A = g_mv + 256; lda = 512;  W = g_Wx;  ldw = 256;  bias = g_bx;  C = g_vproj; ldc = 768; K = 256;  ntn = 12; }
    int tr = blockIdx.x / ntn, tc = blockIdx.x % ntn;
    int row0 = tr * 64, n0 = tc * 64;
    float acc[4][4] = {};
    gemm_tile<16>(A, lda, W, ldw, K, row0, n0, acc);
    int ty = threadIdx.x >> 4, tx = threadIdx.x & 15;
    #pragma unroll
    for (int i = 0; i < 4; i++) {
        int r = row0 + ty * 4 + i;
        #pragma unroll
        for (int j = 0; j < 4; j++) {
            int n = n0 + tx * 4 + j;
            C[(size_t)r * ldc + n] = acc[i][j] + bias[n];
        }
    }
}

// ---------------- per-step kernel A: sim+softmax (blocks 0..31) + r,z GEMM (blocks 32..287) ----------------
__global__ void k_step_a(const float* __restrict__ mem, int t)
{
    if (blockIdx.x < B_) {
        __shared__ float dvec[M_];
        __shared__ float sc[S_];
        int b = blockIdx.x;
        int tid = threadIdx.x, lane = tid & 31, warp = tid >> 5;
        dvec[tid] = g_mv[(size_t)(b * T_ + t) * 512 + tid];   // mem_input row
        __syncthreads();
        #pragma unroll
        for (int si = 0; si < 8; si++) {
            int s = warp * 8 + si;
            const float* mr = mem + (size_t)(b * S_ + s) * M_;
            float p = 0.f;
            for (int k = lane; k < M_; k += 32) p += dvec[k] * mr[k];
            #pragma unroll
            for (int off = 16; off; off >>= 1) p += __shfl_xor_sync(0xffffffffu, p, off);
            if (lane == 0) sc[s] = -p + 0.2f * g_usage[b * S_ + s];   // age term cancels in softmax
        }
        __syncthreads();
        if (tid < 32) {
            float x0 = sc[tid], x1 = sc[tid + 32];
            float mx = fmaxf(x0, x1);
            #pragma unroll
            for (int off = 16; off; off >>= 1) mx = fmaxf(mx, __shfl_xor_sync(0xffffffffu, mx, off));
            float e0 = expf(x0 - mx), e1 = expf(x1 - mx);
            float s = e0 + e1;
            #pragma unroll
            for (int off = 16; off; off >>= 1) s += __shfl_xor_sync(0xffffffffu, s, off);
            float inv = 1.f / s;
            g_ww[b * S_ + tid]      = e0 * inv;
            g_ww[b * S_ + tid + 32] = e1 * inv;
        }
    } else {
        int bx = blockIdx.x - B_;
        int tr = bx >> 3, tc = bx & 7;        // rows 2048/64=32 tiles, cols 512/64=8 tiles
        int row0 = tr * 64, n0 = tc * 64;
        float acc[4][4] = {};
        gemm_tile<16>(mem, M_, g_Wh, M_, M_, row0, n0, acc);
        int b = row0 >> 6;
        const float* vp = g_vproj + (size_t)(b * T_ + t) * 768;
        int ty = threadIdx.x >> 4, tx = threadIdx.x & 15;
        #pragma unroll
        for (int i = 0; i < 4; i++) {
            int r = row0 + ty * 4 + i;
            #pragma unroll
            for (int j = 0; j < 4; j++) {
                int n = n0 + tx * 4 + j;
                float v = 1.f / (1.f + expf(-(acc[i][j] + vp[n])));   // sigmoid
                if (n < 256) g_rm[(size_t)r * M_ + n] = v * mem[(size_t)r * M_ + n];   // r * mem
                else         g_zg[(size_t)r * M_ + (n - 256)] = v;                     // z
            }
        }
    }
}

// ---------------- per-step kernel B: cand GEMM + gated blend (pre-normalization) ----------------
__global__ void k_step_b(float* __restrict__ mem, int t)
{
    int tr = blockIdx.x >> 2, tc = blockIdx.x & 3;   // 32 x 4 tiles
    int row0 = tr * 64, n0 = tc * 64;
    float acc[4][4] = {};
    gemm_tile<16>(g_rm, M_, g_Wh + 512 * M_, M_, M_, row0, n0, acc);
    int b = row0 >> 6;
    const float* vp = g_vproj + (size_t)(b * T_ + t) * 768 + 512;
    int ty = threadIdx.x >> 4, tx = threadIdx.x & 15;
    #pragma unroll
    for (int i = 0; i < 4; i++) {
        int r = row0 + ty * 4 + i;
        float ww = g_ww[r];
        float w = ww * 0.5f;                 // UPDATE_RATE
        bool upd = (ww > 0.01f);
        #pragma unroll
        for (int j = 0; j < 4; j++) {
            int n = n0 + tx * 4 + j;
            float cand = tanhf(acc[i][j] + vp[n]);
            float z = g_zg[(size_t)r * M_ + n];
            float m = mem[(size_t)r * M_ + n];
            float nh = (1.f - z) * m + z * cand;
            float out = upd ? (m * (1.f - w) + nh * w) : m;
            mem[(size_t)r * M_ + n] = out;
        }
    }
}

// ---------------- per-step kernel N: row L2-renormalize + usage update ----------------
__global__ void k_norm(float* __restrict__ mem, int upd)
{
    int row = blockIdx.x, tid = threadIdx.x;
    float v = mem[(size_t)row * M_ + tid];
    float ss = v * v;
    #pragma unroll
    for (int off = 16; off; off >>= 1) ss += __shfl_xor_sync(0xffffffffu, ss, off);
    __shared__ float wsum[8];
    if ((tid & 31) == 0) wsum[tid >> 5] = ss;
    __syncthreads();
    float tot = wsum[0] + wsum[1] + wsum[2] + wsum[3] + wsum[4] + wsum[5] + wsum[6] + wsum[7];
    float scale = 1.f / fmaxf(sqrtf(tot), 1e-12f);
    mem[(size_t)row * M_ + tid] = v * scale;
    if (tid == 0 && upd) {
        float ww = g_ww[row];
        g_usage[row] = (g_usage[row] + (ww > 0.01f ? ww : 0.f)) * 0.99f;
    }
}

// ---------------- init: mem0 = normalize(0.01 * memory_init), usage = 0 ----------------
__global__ void k_init(const float* __restrict__ mi, float* __restrict__ mem)
{
    int row = blockIdx.x, tid = threadIdx.x;
    float v = 0.01f * mi[(size_t)row * M_ + tid];
    float ss = v * v;
    #pragma unroll
    for (int off = 16; off; off >>= 1) ss += __shfl_xor_sync(0xffffffffu, ss, off);
    __shared__ float wsum[8];
    if ((tid & 31) == 0) wsum[tid >> 5] = ss;
    __syncthreads();
    float tot = wsum[0] + wsum[1] + wsum[2] + wsum[3] + wsum[4] + wsum[5] + wsum[6] + wsum[7];
    float scale = 1.f / fmaxf(sqrtf(tot), 1e-12f);
    mem[(size_t)row * M_ + tid] = v * scale;
    if (tid == 0) { g_usage[row] = 0.f; g_ww[row] = 0.f; }
}

// ---------------- launch ----------------
extern "C" void kernel_launch(void* const* d_in, const int* in_sizes, int n_in,
                              void* d_out, int out_size)
{
    const float* hidden  = (const float*)d_in[0];
    const float* meminit = (const float*)d_in[1];
    const float* Wi = (const float*)d_in[2];
    const float* bi = (const float*)d_in[3];
    const float* Wv = (const float*)d_in[4];
    const float* bv = (const float*)d_in[5];
    const float* Wr = (const float*)d_in[6];
    const float* br = (const float*)d_in[7];
    const float* Wz = (const float*)d_in[8];
    const float* bz = (const float*)d_in[9];
    const float* Wu = (const float*)d_in[10];
    const float* bu = (const float*)d_in[11];
    float* mem = (float*)d_out;   // d_out doubles as the live memory state [B,S,M]

    k_pack<<<2048, 256>>>(Wi, bi, Wv, bv, Wr, br, Wz, bz, Wu, bu);
    k_init<<<ROWS_, 256>>>(meminit, mem);
    k_gemm_pre<<<128 * 8, 256>>>(hidden, 0);    // mem_input | vals
    k_gemm_pre<<<128 * 12, 256>>>(hidden, 1);   // VR | VZ | VU

    for (int t = 0; t < T_; t++) {
        k_step_a<<<B_ + 256, 256>>>(mem, t);    // sim/softmax + r,z
        k_step_b<<<128, 256>>>(mem, t);         // cand + gated blend
        k_norm<<<ROWS_, 256>>>(mem, 1);         // renormalize + usage
    }
}

// round 2
// speedup vs baseline: 1.0201x; 1.0201x over previous
#include <cuda_runtime.h>
#include <math.h>

// Problem constants
#define B_  32
#define T_  256
#define D_  1024
#define M_  256
#define S_  64
#define ROWS_ (B_*S_)     // 2048
#define BT_  (B_*T_)      // 8192

// ---------------- scratch (static device globals; no allocation) ----------------
// g_mv: [BT, 512] : cols [0,256) = mem_input (x@Wi.T+bi), cols [256,512) = vals (x@Wv.T+bv)
__device__ float g_mv[(size_t)BT_ * 512];
// g_vproj: [BT, 768] : vals @ {Wr_x,Wz_x,Wu_x}.T + {br,bz,bu}  (gate-major: 0..255 r, 256..511 z, 512..767 u)
__device__ float g_vproj[(size_t)BT_ * 768];
// per-step intermediates
__device__ float g_rm[(size_t)ROWS_ * M_];   // r * mem
__device__ float g_zg[(size_t)ROWS_ * M_];   // z gate
__device__ float g_ww[ROWS_];                // write weights (softmax)
__device__ float g_usage[ROWS_];             // usage state
// packed weights
__device__ float g_Wiv[(size_t)512 * D_];    // rows 0..255 Wi, 256..511 Wv   [512,1024]
__device__ float g_biv[512];
__device__ float g_Wx[(size_t)768 * M_];     // x-halves of Wr,Wz,Wu  [768,256]
__device__ float g_Wh[(size_t)768 * M_];     // h-halves of Wr,Wz,Wu  [768,256]
__device__ float g_bx[768];

// ---------------- pack kernel ----------------
__global__ void k_pack(const float* __restrict__ Wi, const float* __restrict__ bi,
                       const float* __restrict__ Wv, const float* __restrict__ bv,
                       const float* __restrict__ Wr, const float* __restrict__ br,
                       const float* __restrict__ Wz, const float* __restrict__ bz,
                       const float* __restrict__ Wu, const float* __restrict__ bu)
{
    int idx = blockIdx.x * blockDim.x + threadIdx.x;   // grid covers 524288
    if (idx < 512 * 1024) {
        int r = idx >> 10, k = idx & 1023;
        g_Wiv[idx] = (r < 256) ? Wi[r * 1024 + k] : Wv[(r - 256) * 1024 + k];
    }
    if (idx < 768 * 256) {
        int n = idx >> 8, k = idx & 255;
        int gate = n >> 8, j = n & 255;
        const float* Wg = (gate == 0) ? Wr : ((gate == 1) ? Wz : Wu);
        g_Wx[idx] = Wg[j * 512 + k];
        g_Wh[idx] = Wg[j * 512 + 256 + k];
    }
    if (idx < 768) {
        g_bx[idx] = (idx < 256) ? br[idx] : ((idx < 512) ? bz[idx - 256] : bu[idx - 512]);
    }
    if (idx < 512) {
        g_biv[idx] = (idx < 256) ? bi[idx] : bv[idx - 256];
    }
}

// ---------------- shared 64x64x16 fp32 GEMM tile core ----------------
// acc[i][j] += sum_k A[row0+ty*4+i][k] * W[n0+tx*4+j][k]   (both operands K-major)
template<int KTILE>
__device__ __forceinline__ void gemm_tile(const float* __restrict__ A, int lda,
                                          const float* __restrict__ W, int ldw,
                                          int K, int row0, int n0, float acc[4][4])
{
    __shared__ float sA[KTILE][68];
    __shared__ float sW[KTILE][68];
    const int tid = threadIdx.x;
    const int lr = tid >> 2;            // 0..63
    const int lk = (tid & 3) * 4;       // 0,4,8,12
    const int ty = tid >> 4;            // 0..15
    const int tx = tid & 15;            // 0..15
    for (int k0 = 0; k0 < K; k0 += KTILE) {
        float4 av = *(const float4*)(A + (size_t)(row0 + lr) * lda + k0 + lk);
        float4 wv = *(const float4*)(W + (size_t)(n0 + lr) * ldw + k0 + lk);
        __syncthreads();
        sA[lk + 0][lr] = av.x; sA[lk + 1][lr] = av.y; sA[lk + 2][lr] = av.z; sA[lk + 3][lr] = av.w;
        sW[lk + 0][lr] = wv.x; sW[lk + 1][lr] = wv.y; sW[lk + 2][lr] = wv.z; sW[lk + 3][lr] = wv.w;
        __syncthreads();
        #pragma unroll
        for (int kk = 0; kk < KTILE; kk++) {
            float4 a = *(const float4*)&sA[kk][ty * 4];
            float4 w = *(const float4*)&sW[kk][tx * 4];
            float ar[4] = {a.x, a.y, a.z, a.w};
            float wr[4] = {w.x, w.y, w.z, w.w};
            #pragma unroll
            for (int i = 0; i < 4; i++)
                #pragma unroll
                for (int j = 0; j < 4; j++)
                    acc[i][j] = fmaf(ar[i], wr[j], acc[i][j]);
        }
    }
}

// ---------------- precompute GEMMs ----------------
// mode 0: g_mv[8192,512]   = hidden[8192,1024] @ g_Wiv.T + g_biv
// mode 1: g_vproj[8192,768] = vals[8192,256]    @ g_Wx.T  + g_bx
__global__ void k_gemm_pre(const float* __restrict__ hidden, int mode)
{
    const float* A; const float* W; const float* bias; float* C;
    int lda, ldw, ldc, K, ntn;
    if (mode == 0) { A = hidden;     lda = 1024; W = g_Wiv; ldw = 1024; bias = g_biv; C = g_mv;    ldc = 512; K = 1024; ntn = 8;  }
    else           { A = g_mv + 256; lda = 512;  W = g_Wx;  ldw = 256;  bias = g_bx;  C = g_vproj; ldc = 768; K = 256;  ntn = 12; }
    int tr = blockIdx.x / ntn, tc = blockIdx.x % ntn;
    int row0 = tr * 64, n0 = tc * 64;
    float acc[4][4] = {};
    gemm_tile<16>(A, lda, W, ldw, K, row0, n0, acc);
    int ty = threadIdx.x >> 4, tx = threadIdx.x & 15;
    #pragma unroll
    for (int i = 0; i < 4; i++) {
        int r = row0 + ty * 4 + i;
        #pragma unroll
        for (int j = 0; j < 4; j++) {
            int n = n0 + tx * 4 + j;
            C[(size_t)r * ldc + n] = acc[i][j] + bias[n];
        }
    }
}

// ---------------- per-step kernel A: sim+softmax (blocks 0..31) + r,z GEMM (blocks 32..287) ----------------
__global__ void k_step_a(const float* __restrict__ mem, int t)
{
    if (blockIdx.x < B_) {
        __shared__ float dvec[M_];
        __shared__ float sc[S_];
        int b = blockIdx.x;
        int tid = threadIdx.x, lane = tid & 31, warp = tid >> 5;
        dvec[tid] = g_mv[(size_t)(b * T_ + t) * 512 + tid];   // mem_input row
        __syncthreads();
        #pragma unroll
        for (int si = 0; si < 8; si++) {
            int s = warp * 8 + si;
            const float* mr = mem + (size_t)(b * S_ + s) * M_;
            float p = 0.f;
            for (int k = lane; k < M_; k += 32) p += dvec[k] * mr[k];
            #pragma unroll
            for (int off = 16; off; off >>= 1) p += __shfl_xor_sync(0xffffffffu, p, off);
            if (lane == 0) sc[s] = -p + 0.2f * g_usage[b * S_ + s];   // age term cancels in softmax
        }
        __syncthreads();
        if (tid < 32) {
            float x0 = sc[tid], x1 = sc[tid + 32];
            float mx = fmaxf(x0, x1);
            #pragma unroll
            for (int off = 16; off; off >>= 1) mx = fmaxf(mx, __shfl_xor_sync(0xffffffffu, mx, off));
            float e0 = expf(x0 - mx), e1 = expf(x1 - mx);
            float s = e0 + e1;
            #pragma unroll
            for (int off = 16; off; off >>= 1) s += __shfl_xor_sync(0xffffffffu, s, off);
            float inv = 1.f / s;
            g_ww[b * S_ + tid]      = e0 * inv;
            g_ww[b * S_ + tid + 32] = e1 * inv;
        }
    } else {
        int bx = blockIdx.x - B_;
        int tr = bx >> 3, tc = bx & 7;        // rows 2048/64=32 tiles, cols 512/64=8 tiles
        int row0 = tr * 64, n0 = tc * 64;
        float acc[4][4] = {};
        gemm_tile<16>(mem, M_, g_Wh, M_, M_, row0, n0, acc);
        int b = row0 >> 6;
        const float* vp = g_vproj + (size_t)(b * T_ + t) * 768;
        int ty = threadIdx.x >> 4, tx = threadIdx.x & 15;
        #pragma unroll
        for (int i = 0; i < 4; i++) {
            int r = row0 + ty * 4 + i;
            #pragma unroll
            for (int j = 0; j < 4; j++) {
                int n = n0 + tx * 4 + j;
                float v = 1.f / (1.f + expf(-(acc[i][j] + vp[n])));   // sigmoid
                if (n < 256) g_rm[(size_t)r * M_ + n] = v * mem[(size_t)r * M_ + n];   // r * mem
                else         g_zg[(size_t)r * M_ + (n - 256)] = v;                     // z
            }
        }
    }
}

// ---------------- per-step kernel B: cand GEMM + gated blend (pre-normalization) ----------------
__global__ void k_step_b(float* __restrict__ mem, int t)
{
    int tr = blockIdx.x >> 2, tc = blockIdx.x & 3;   // 32 x 4 tiles
    int row0 = tr * 64, n0 = tc * 64;
    float acc[4][4] = {};
    gemm_tile<16>(g_rm, M_, g_Wh + 512 * M_, M_, M_, row0, n0, acc);
    int b = row0 >> 6;
    const float* vp = g_vproj + (size_t)(b * T_ + t) * 768 + 512;
    int ty = threadIdx.x >> 4, tx = threadIdx.x & 15;
    #pragma unroll
    for (int i = 0; i < 4; i++) {
        int r = row0 + ty * 4 + i;
        float ww = g_ww[r];
        float w = ww * 0.5f;                 // UPDATE_RATE
        bool upd = (ww > 0.01f);
        #pragma unroll
        for (int j = 0; j < 4; j++) {
            int n = n0 + tx * 4 + j;
            float cand = tanhf(acc[i][j] + vp[n]);
            float z = g_zg[(size_t)r * M_ + n];
            float m = mem[(size_t)r * M_ + n];
            float nh = (1.f - z) * m + z * cand;
            float out = upd ? (m * (1.f - w) + nh * w) : m;
            mem[(size_t)r * M_ + n] = out;
        }
    }
}

// ---------------- per-step kernel N: row L2-renormalize + usage update ----------------
__global__ void k_norm(float* __restrict__ mem, int upd)
{
    int row = blockIdx.x, tid = threadIdx.x;
    float v = mem[(size_t)row * M_ + tid];
    float ss = v * v;
    #pragma unroll
    for (int off = 16; off; off >>= 1) ss += __shfl_xor_sync(0xffffffffu, ss, off);
    __shared__ float wsum[8];
    if ((tid & 31) == 0) wsum[tid >> 5] = ss;
    __syncthreads();
    float tot = wsum[0] + wsum[1] + wsum[2] + wsum[3] + wsum[4] + wsum[5] + wsum[6] + wsum[7];
    float scale = 1.f / fmaxf(sqrtf(tot), 1e-12f);
    mem[(size_t)row * M_ + tid] = v * scale;
    if (tid == 0 && upd) {
        float ww = g_ww[row];
        g_usage[row] = (g_usage[row] + (ww > 0.01f ? ww : 0.f)) * 0.99f;
    }
}

// ---------------- init: mem0 = normalize(0.01 * memory_init), usage = 0 ----------------
__global__ void k_init(const float* __restrict__ mi, float* __restrict__ mem)
{
    int row = blockIdx.x, tid = threadIdx.x;
    float v = 0.01f * mi[(size_t)row * M_ + tid];
    float ss = v * v;
    #pragma unroll
    for (int off = 16; off; off >>= 1) ss += __shfl_xor_sync(0xffffffffu, ss, off);
    __shared__ float wsum[8];
    if ((tid & 31) == 0) wsum[tid >> 5] = ss;
    __syncthreads();
    float tot = wsum[0] + wsum[1] + wsum[2] + wsum[3] + wsum[4] + wsum[5] + wsum[6] + wsum[7];
    float scale = 1.f / fmaxf(sqrtf(tot), 1e-12f);
    mem[(size_t)row * M_ + tid] = v * scale;
    if (tid == 0) { g_usage[row] = 0.f; g_ww[row] = 0.f; }
}

// ---------------- launch ----------------
extern "C" void kernel_launch(void* const* d_in, const int* in_sizes, int n_in,
                              void* d_out, int out_size)
{
    const float* hidden  = (const float*)d_in[0];
    const float* meminit = (const float*)d_in[1];
    const float* Wi = (const float*)d_in[2];
    const float* bi = (const float*)d_in[3];
    const float* Wv = (const float*)d_in[4];
    const float* bv = (const float*)d_in[5];
    const float* Wr = (const float*)d_in[6];
    const float* br = (const float*)d_in[7];
    const float* Wz = (const float*)d_in[8];
    const float* bz = (const float*)d_in[9];
    const float* Wu = (const float*)d_in[10];
    const float* bu = (const float*)d_in[11];
    float* mem = (float*)d_out;   // d_out doubles as the live memory state [B,S,M]

    k_pack<<<2048, 256>>>(Wi, bi, Wv, bv, Wr, br, Wz, bz, Wu, bu);
    k_init<<<ROWS_, 256>>>(meminit, mem);
    k_gemm_pre<<<128 * 8, 256>>>(hidden, 0);    // mem_input | vals
    k_gemm_pre<<<128 * 12, 256>>>(hidden, 1);   // VR | VZ | VU

    for (int t = 0; t < T_; t++) {
        k_step_a<<<B_ + 256, 256>>>(mem, t);    // sim/softmax + r,z
        k_step_b<<<128, 256>>>(mem, t);         // cand + gated blend
        k_norm<<<ROWS_, 256>>>(mem, 1);         // renormalize + usage
    }
}